// round 1
// baseline (speedup 1.0000x reference)
#include <cuda_runtime.h>

// Static problem shapes (from setup_inputs)
constexpr int kS   = 2;
constexpr int kVin = 3;
constexpr int kVt  = 4;
constexpr int kC   = 16;
constexpr int kD   = 64;
constexpr int kH   = 96;
constexpr int kW   = 96;
constexpr int kHlo = 48;
constexpr int kWlo = 48;
constexpr int kSpr = 64;

constexpr int kDHW  = kD * kH * kW;          // 589824
constexpr int kNVox = kS * kVin * kDHW;      // 3,538,944
constexpr int kRays = kS * kVt * kHlo * kWlo; // 18432

// Scratch: channel-last transposed volume + low-res renders
__device__ float g_encT[(size_t)kNVox * kC];           // 226 MB
__device__ float g_rlo[kS * kVt * kC * kHlo * kWlo];   // 1.18 MB

// ---------------------------------------------------------------------------
// Kernel 1: transpose encoded_imgs (S,Vin,C,D,H,W) -> (S*Vin, D,H,W, C)
// Reads perfectly coalesced per channel plane; writes 64B/thread contiguous.
// ---------------------------------------------------------------------------
__global__ void transpose_kernel(const float* __restrict__ enc) {
    int vox = blockIdx.x * blockDim.x + threadIdx.x;
    if (vox >= kNVox) return;
    int sv = vox / kDHW;
    int p  = vox - sv * kDHW;
    const float* src = enc + (size_t)sv * kC * kDHW + p;
    float v[kC];
#pragma unroll
    for (int c = 0; c < kC; c++) v[c] = src[(size_t)c * kDHW];
    float4* dst = reinterpret_cast<float4*>(g_encT + (size_t)vox * kC);
    dst[0] = make_float4(v[0], v[1], v[2], v[3]);
    dst[1] = make_float4(v[4], v[5], v[6], v[7]);
    dst[2] = make_float4(v[8], v[9], v[10], v[11]);
    dst[3] = make_float4(v[12], v[13], v[14], v[15]);
}

// ---------------------------------------------------------------------------
// Kernel 2: fused ray kernel. Block = 256 threads = 4 rays x 64 samples.
// Per thread: ray point -> 3-view trilinear gather -> MLP -> alpha compositing
// via block-local inclusive scan + per-channel reduction.
// ---------------------------------------------------------------------------
__global__ __launch_bounds__(256) void render_kernel(
    const float* __restrict__ tposes,   // (S,Vt,4,4)
    const float* __restrict__ iposes,   // (S,Vin,4,4)
    const float* __restrict__ fp,
    const float* __restrict__ znp,
    const float* __restrict__ zfp,
    const float* __restrict__ W1, const float* __restrict__ b1,
    const float* __restrict__ W2, const float* __restrict__ b2,
    const float* __restrict__ W3, const float* __restrict__ b3)
{
    __shared__ float sW1t[64 * 16];   // transposed: [j][c]
    __shared__ float sB1[64];
    __shared__ float sW2[64 * 64];    // [j][k]
    __shared__ float sB2[64];
    __shared__ float sW3[64 * 17];    // [j][m]
    __shared__ float sB3[17];
    __shared__ float sWS[4][2];       // per-ray warp partial sums (scan)
    __shared__ float sRed[4][2][16];  // per-ray per-warp channel partials

    const int tid = threadIdx.x;

    // Stage weights into shared
    for (int i = tid; i < 1024; i += 256) {
        int j = i >> 4, c = i & 15;
        sW1t[i] = W1[c * 64 + j];
    }
    for (int i = tid; i < 4096; i += 256) sW2[i] = W2[i];
    for (int i = tid; i < 1088; i += 256) sW3[i] = W3[i];
    if (tid < 64) { sB1[tid] = b1[tid]; sB2[tid] = b2[tid]; }
    if (tid < 17) sB3[tid] = b3[tid];
    __syncthreads();

    const int rb = tid >> 6;          // ray within block (0..3)
    const int rt = tid & 63;          // sample index along ray
    const int lane = rt & 31;
    const int wr = rt >> 5;           // warp within ray (0/1)

    const int ray = blockIdx.x * 4 + rb;
    const int sv  = ray / (kHlo * kWlo);     // s*Vt + vt
    const int pix = ray - sv * (kHlo * kWlo);
    const int py  = pix / kWlo;
    const int px  = pix - py * kWlo;
    const int s   = sv / kVt;

    const float focal = *fp;
    const float zn = *znp, zf = *zfp;

    // Ray origin/direction from target pose
    const float* P = tposes + sv * 16;
    const float dcx = ((((float)px + 0.5f) / kWlo) * 2.0f - 1.0f) / focal;
    const float dcy = -(((((float)py + 0.5f) / kHlo) * 2.0f - 1.0f) / focal);
    const float dcz = -1.0f;
    const float dirx = P[0] * dcx + P[1] * dcy + P[2]  * dcz;
    const float diry = P[4] * dcx + P[5] * dcy + P[6]  * dcz;
    const float dirz = P[8] * dcx + P[9] * dcy + P[10] * dcz;
    const float ox = P[3], oy = P[7], oz = P[11];

    const float t = zn + (zf - zn) * ((float)rt / 63.0f);
    const float ptx = ox + t * dirx;
    const float pty = oy + t * diry;
    const float ptz = oz + t * dirz;

    const float minz = focal * zn;
    const float maxz = focal * zf;
    const float wdscale = 2.0f / (maxz - minz);

    // --- 3-view trilinear gather (channel-last volume) ---
    float4 fa0 = make_float4(0.f, 0.f, 0.f, 0.f);
    float4 fa1 = fa0, fa2 = fa0, fa3 = fa0;

#pragma unroll
    for (int v = 0; v < kVin; v++) {
        const float* IP = iposes + (s * kVin + v) * 16;
        const float dx = ptx - IP[3];
        const float dy = pty - IP[7];
        const float dz = ptz - IP[11];
        // local = R^T (pt - tr)
        const float lx = IP[0] * dx + IP[4] * dy + IP[8]  * dz;
        const float ly = IP[1] * dx + IP[5] * dy + IP[9]  * dz;
        const float lz = IP[2] * dx + IP[6] * dy + IP[10] * dz;
        const float z  = -lz;
        const float invz = focal / z;
        const float u  = lx * invz;
        const float vv = ly * invz;
        const float wd = (z - minz) * wdscale - 1.0f;
        const float gx = u, gy = -vv, gz = -wd;

        const float ixf = (gx + 1.0f) * (0.5f * kW) - 0.5f;
        const float iyf = (gy + 1.0f) * (0.5f * kH) - 0.5f;
        const float izf = (gz + 1.0f) * (0.5f * kD) - 0.5f;

        const float xf0 = floorf(ixf);
        const float yf0 = floorf(iyf);
        const float zf0 = floorf(izf);
        const int ix0 = (int)xf0, iy0 = (int)yf0, iz0 = (int)zf0;
        const float fx = ixf - xf0, fy = iyf - yf0, fz = izf - zf0;

        const int svin = s * kVin + v;
#pragma unroll
        for (int dzi = 0; dzi < 2; dzi++) {
            const int zc = iz0 + dzi;
            if ((unsigned)zc >= (unsigned)kD) continue;
            const float wz = dzi ? fz : (1.0f - fz);
#pragma unroll
            for (int dyi = 0; dyi < 2; dyi++) {
                const int yc = iy0 + dyi;
                if ((unsigned)yc >= (unsigned)kH) continue;
                const float wzy = wz * (dyi ? fy : (1.0f - fy));
                const size_t rowb = ((size_t)(svin * kD + zc) * kH + yc) * kW;
#pragma unroll
                for (int dxi = 0; dxi < 2; dxi++) {
                    const int xc = ix0 + dxi;
                    if ((unsigned)xc >= (unsigned)kW) continue;
                    const float wgt = wzy * (dxi ? fx : (1.0f - fx));
                    const float4* pv = reinterpret_cast<const float4*>(
                        g_encT + (rowb + xc) * kC);
                    float4 a = pv[0], b_ = pv[1], c_ = pv[2], d_ = pv[3];
                    fa0.x += wgt * a.x;  fa0.y += wgt * a.y;
                    fa0.z += wgt * a.z;  fa0.w += wgt * a.w;
                    fa1.x += wgt * b_.x; fa1.y += wgt * b_.y;
                    fa1.z += wgt * b_.z; fa1.w += wgt * b_.w;
                    fa2.x += wgt * c_.x; fa2.y += wgt * c_.y;
                    fa2.z += wgt * c_.z; fa2.w += wgt * c_.w;
                    fa3.x += wgt * d_.x; fa3.y += wgt * d_.y;
                    fa3.z += wgt * d_.z; fa3.w += wgt * d_.w;
                }
            }
        }
    }

    const float inv3 = 1.0f / 3.0f;
    float feats[16] = {
        fa0.x * inv3, fa0.y * inv3, fa0.z * inv3, fa0.w * inv3,
        fa1.x * inv3, fa1.y * inv3, fa1.z * inv3, fa1.w * inv3,
        fa2.x * inv3, fa2.y * inv3, fa2.z * inv3, fa2.w * inv3,
        fa3.x * inv3, fa3.y * inv3, fa3.z * inv3, fa3.w * inv3 };

    // --- MLP 16 -> 64 -> 64 -> 17 (streamed, hidden stays in regs) ---
    float4 a2[16];
#pragma unroll
    for (int k = 0; k < 16; k++) {
        a2[k] = make_float4(sB2[4 * k], sB2[4 * k + 1], sB2[4 * k + 2], sB2[4 * k + 3]);
    }
#pragma unroll 4
    for (int j = 0; j < 64; j++) {
        float a = sB1[j];
        const float* w1r = sW1t + j * 16;
#pragma unroll
        for (int c = 0; c < 16; c++) a += feats[c] * w1r[c];
        a = fmaxf(a, 0.0f);
        const float4* w2r = reinterpret_cast<const float4*>(sW2 + j * 64);
#pragma unroll
        for (int k = 0; k < 16; k++) {
            float4 w = w2r[k];
            a2[k].x += a * w.x; a2[k].y += a * w.y;
            a2[k].z += a * w.z; a2[k].w += a * w.w;
        }
    }
    float o[17];
#pragma unroll
    for (int m = 0; m < 17; m++) o[m] = sB3[m];
#pragma unroll
    for (int k = 0; k < 16; k++) {
        float hh[4] = { a2[k].x, a2[k].y, a2[k].z, a2[k].w };
#pragma unroll
        for (int q = 0; q < 4; q++) {
            const float hv = fmaxf(hh[q], 0.0f);
            const float* w3r = sW3 + (k * 4 + q) * 17;
#pragma unroll
            for (int m = 0; m < 17; m++) o[m] += hv * w3r[m];
        }
    }

    const float density = fmaxf(o[0], 0.0f);
    const float delta = (rt == 63) ? 1e10f : (zf - zn) * (1.0f / 63.0f);
    const float sd = density * delta;

    // Inclusive scan of sd across the 64 threads of this ray
    float vscan = sd;
#pragma unroll
    for (int off = 1; off < 32; off <<= 1) {
        float n = __shfl_up_sync(0xffffffffu, vscan, off);
        if (lane >= off) vscan += n;
    }
    if (lane == 31) sWS[rb][wr] = vscan;
    __syncthreads();
    const float cum = vscan + ((wr == 1) ? sWS[rb][0] : 0.0f);
    const float T = expf(-cum);
    const float alpha = 1.0f - expf(-sd);
    const float wgt = alpha * T;

    // Per-channel weighted reduction over the 64 samples
#pragma unroll
    for (int c = 0; c < 16; c++) {
        float val = wgt * (feats[c] + o[c + 1]);
#pragma unroll
        for (int off = 16; off > 0; off >>= 1)
            val += __shfl_down_sync(0xffffffffu, val, off);
        if (lane == 0) sRed[rb][wr][c] = val;
    }
    __syncthreads();
    if (rt < 16) {
        g_rlo[((sv * kC + rt) * kHlo + py) * kWlo + px] =
            sRed[rb][0][rt] + sRed[rb][1][rt];
    }
}

// ---------------------------------------------------------------------------
// Kernel 3: 2x bilinear upsample, align_corners=True (48 -> 96)
// ---------------------------------------------------------------------------
__global__ void upsample_kernel(float* __restrict__ out) {
    const int n = blockIdx.x * blockDim.x + threadIdx.x;
    constexpr int kTot = kS * kVt * kC * kH * kW;
    if (n >= kTot) return;
    const int x = n % kW;
    const int y = (n / kW) % kH;
    const int svc = n / (kH * kW);

    const float pxf = (float)x * (47.0f / 95.0f);
    const float pyf = (float)y * (47.0f / 95.0f);
    const int lx = (int)pxf; const int hx = min(lx + 1, 47);
    const int ly = (int)pyf; const int hy = min(ly + 1, 47);
    const float fx = pxf - (float)lx;
    const float fy = pyf - (float)ly;

    const float* r = g_rlo + svc * (kHlo * kWlo);
    const float v00 = r[ly * kWlo + lx];
    const float v01 = r[ly * kWlo + hx];
    const float v10 = r[hy * kWlo + lx];
    const float v11 = r[hy * kWlo + hx];
    out[n] = (v00 * (1.0f - fx) + v01 * fx) * (1.0f - fy)
           + (v10 * (1.0f - fx) + v11 * fx) * fy;
}

// ---------------------------------------------------------------------------
extern "C" void kernel_launch(void* const* d_in, const int* in_sizes, int n_in,
                              void* d_out, int out_size) {
    const float* enc = (const float*)d_in[0];
    const float* ipo = (const float*)d_in[1];
    const float* tpo = (const float*)d_in[2];
    const float* fp  = (const float*)d_in[3];
    const float* znp = (const float*)d_in[4];
    const float* zfp = (const float*)d_in[5];
    // d_in[6] = samples_per_ray (int32, statically 64)
    const float* W1 = (const float*)d_in[7];
    const float* b1 = (const float*)d_in[8];
    const float* W2 = (const float*)d_in[9];
    const float* b2 = (const float*)d_in[10];
    const float* W3 = (const float*)d_in[11];
    const float* b3 = (const float*)d_in[12];
    float* out = (float*)d_out;

    transpose_kernel<<<(kNVox + 255) / 256, 256>>>(enc);
    render_kernel<<<kRays / 4, 256>>>(tpo, ipo, fp, znp, zfp,
                                      W1, b1, W2, b2, W3, b3);
    constexpr int kTot = kS * kVt * kC * kH * kW;
    upsample_kernel<<<(kTot + 255) / 256, 256>>>(out);
}

// round 2
// speedup vs baseline: 1.3626x; 1.3626x over previous
#include <cuda_runtime.h>
#include <cuda_fp16.h>

// Static problem shapes (from setup_inputs)
constexpr int kS   = 2;
constexpr int kVin = 3;
constexpr int kVt  = 4;
constexpr int kC   = 16;
constexpr int kD   = 64;
constexpr int kH   = 96;
constexpr int kW   = 96;
constexpr int kHlo = 48;
constexpr int kWlo = 48;

constexpr int kDHW  = kD * kH * kW;           // 589824
constexpr int kNVox = kS * kVin * kDHW;       // 3,538,944
constexpr int kRays = kS * kVt * kHlo * kWlo; // 18432

// Scratch: channel-last fp16 volume (113 MB, fits L2) + low-res renders
__device__ __half g_encT[(size_t)kNVox * kC];
__device__ float  g_rlo[kS * kVt * kC * kHlo * kWlo];

// ---------------- packed f32x2 helpers (sm_103a) ----------------
using u64 = unsigned long long;
__device__ __forceinline__ u64 pack2(float lo, float hi) {
    u64 r; asm("mov.b64 %0,{%1,%2};" : "=l"(r) : "f"(lo), "f"(hi)); return r;
}
__device__ __forceinline__ float2 unpack2(u64 v) {
    float2 f; asm("mov.b64 {%0,%1},%2;" : "=f"(f.x), "=f"(f.y) : "l"(v)); return f;
}
__device__ __forceinline__ u64 ffma2(u64 a, u64 b, u64 c) {
    u64 d; asm("fma.rn.f32x2 %0,%1,%2,%3;" : "=l"(d) : "l"(a), "l"(b), "l"(c)); return d;
}
__device__ __forceinline__ u64 fmul2(u64 a, u64 b) {
    u64 d; asm("mul.rn.f32x2 %0,%1,%2;" : "=l"(d) : "l"(a), "l"(b)); return d;
}
__device__ __forceinline__ u64 h2f2p(unsigned u) {
    __half2 h = *reinterpret_cast<__half2*>(&u);
    float2 f = __half22float2(h);
    return pack2(f.x, f.y);
}

// ---------------------------------------------------------------------------
// Kernel 1: transpose encoded_imgs (S,Vin,C,D,H,W) fp32 -> (S*Vin,D,H,W,C) fp16
// ---------------------------------------------------------------------------
__global__ void transpose_kernel(const float* __restrict__ enc) {
    int vox = blockIdx.x * blockDim.x + threadIdx.x;
    if (vox >= kNVox) return;
    int sv = vox / kDHW;
    int p  = vox - sv * kDHW;
    const float* src = enc + sv * (kC * kDHW) + p;
    unsigned h[8];
#pragma unroll
    for (int i = 0; i < 8; i++) {
        float a = src[(2 * i) * kDHW];
        float b = src[(2 * i + 1) * kDHW];
        __half2 hh = __floats2half2_rn(a, b);
        h[i] = *reinterpret_cast<unsigned*>(&hh);
    }
    uint4* dst = reinterpret_cast<uint4*>(g_encT + (size_t)vox * kC);
    dst[0] = make_uint4(h[0], h[1], h[2], h[3]);
    dst[1] = make_uint4(h[4], h[5], h[6], h[7]);
}

// ---------------------------------------------------------------------------
// Kernel 2: fused ray kernel. Block = 256 threads = 4 rays x 64 samples.
// ---------------------------------------------------------------------------
__global__ __launch_bounds__(256, 2) void render_kernel(
    const float* __restrict__ tposes,
    const float* __restrict__ iposes,
    const float* __restrict__ fp,
    const float* __restrict__ znp,
    const float* __restrict__ zfp,
    const float* __restrict__ W1, const float* __restrict__ b1,
    const float* __restrict__ W2, const float* __restrict__ b2,
    const float* __restrict__ W3, const float* __restrict__ b3)
{
    __shared__ u64   sW1p[64 * 8];    // [j][cpair]
    __shared__ u64   sW2p[64 * 32];   // [j][kpair]
    __shared__ u64   sW3p[64 * 8];    // [j][mpair]  (m=0..15)
    __shared__ float sW3l[64];        // W3[j][16]
    __shared__ float sB1[64], sB2[64], sB3[17];
    __shared__ float sWS[4][2];
    __shared__ float sRed[4][2][16];

    const int tid = threadIdx.x;

    // Stage weights (packed) into shared
    for (int i = tid; i < 512; i += 256) {
        int j = i >> 3, cp = i & 7;
        sW1p[i] = pack2(W1[(2 * cp) * 64 + j], W1[(2 * cp + 1) * 64 + j]);
    }
    {
        const u64* W2u = reinterpret_cast<const u64*>(W2);
        for (int i = tid; i < 2048; i += 256) sW2p[i] = W2u[i];
    }
    for (int i = tid; i < 512; i += 256) {
        int j = i >> 3, mp = i & 7;
        sW3p[i] = pack2(W3[j * 17 + 2 * mp], W3[j * 17 + 2 * mp + 1]);
    }
    if (tid < 64) {
        sB1[tid] = b1[tid];
        sB2[tid] = b2[tid];
        sW3l[tid] = W3[tid * 17 + 16];
    }
    if (tid < 17) sB3[tid] = b3[tid];
    __syncthreads();

    const int rb = tid >> 6;          // ray within block (0..3)
    const int rt = tid & 63;          // sample index along ray
    const int lane = rt & 31;
    const int wr = rt >> 5;

    const int ray = blockIdx.x * 4 + rb;
    const int sv  = ray / (kHlo * kWlo);
    const int pix = ray - sv * (kHlo * kWlo);
    const int py  = pix / kWlo;
    const int px  = pix - py * kWlo;
    const int s   = sv / kVt;

    const float focal = *fp;
    const float zn = *znp, zf = *zfp;

    const float* P = tposes + sv * 16;
    const float dcx = ((((float)px + 0.5f) / kWlo) * 2.0f - 1.0f) / focal;
    const float dcy = -(((((float)py + 0.5f) / kHlo) * 2.0f - 1.0f) / focal);
    const float dcz = -1.0f;
    const float dirx = P[0] * dcx + P[1] * dcy + P[2]  * dcz;
    const float diry = P[4] * dcx + P[5] * dcy + P[6]  * dcz;
    const float dirz = P[8] * dcx + P[9] * dcy + P[10] * dcz;

    const float t = zn + (zf - zn) * ((float)rt / 63.0f);
    const float ptx = P[3] + t * dirx;
    const float pty = P[7] + t * diry;
    const float ptz = P[11] + t * dirz;

    const float minz = focal * zn;
    const float maxz = focal * zf;
    const float wdscale = 2.0f / (maxz - minz);

    // --- 3-view trilinear gather (channel-last fp16 volume) ---
    u64 fa[8];
#pragma unroll
    for (int i = 0; i < 8; i++) fa[i] = 0ull;

#pragma unroll
    for (int v = 0; v < kVin; v++) {
        const float* IP = iposes + (s * kVin + v) * 16;
        const float dx = ptx - IP[3];
        const float dy = pty - IP[7];
        const float dz = ptz - IP[11];
        const float lx = IP[0] * dx + IP[4] * dy + IP[8]  * dz;
        const float ly = IP[1] * dx + IP[5] * dy + IP[9]  * dz;
        const float lz = IP[2] * dx + IP[6] * dy + IP[10] * dz;
        const float z  = -lz;
        const float invz = focal / z;
        const float gx = lx * invz;
        const float gy = -(ly * invz);
        const float gz = -((z - minz) * wdscale - 1.0f);

        const float ixf = (gx + 1.0f) * (0.5f * kW) - 0.5f;
        const float iyf = (gy + 1.0f) * (0.5f * kH) - 0.5f;
        const float izf = (gz + 1.0f) * (0.5f * kD) - 0.5f;

        const float xf0 = floorf(ixf), yf0 = floorf(iyf), zf0 = floorf(izf);
        const int ix0 = (int)xf0, iy0 = (int)yf0, iz0 = (int)zf0;
        const float fx = ixf - xf0, fy = iyf - yf0, fz = izf - zf0;

        const int svin = s * kVin + v;
#pragma unroll
        for (int dzi = 0; dzi < 2; dzi++) {
            const int zc = iz0 + dzi;
            if ((unsigned)zc >= (unsigned)kD) continue;
            const float wz = dzi ? fz : (1.0f - fz);
#pragma unroll
            for (int dyi = 0; dyi < 2; dyi++) {
                const int yc = iy0 + dyi;
                if ((unsigned)yc >= (unsigned)kH) continue;
                const float wzy = wz * (dyi ? fy : (1.0f - fy));
                const int rowb = ((svin * kD + zc) * kH + yc) * kW;
#pragma unroll
                for (int dxi = 0; dxi < 2; dxi++) {
                    const int xc = ix0 + dxi;
                    if ((unsigned)xc >= (unsigned)kW) continue;
                    const float wgt = wzy * (dxi ? fx : (1.0f - fx));
                    const uint4* pv = reinterpret_cast<const uint4*>(
                        g_encT + (size_t)(rowb + xc) * kC);
                    uint4 q0 = pv[0];
                    uint4 q1 = pv[1];
                    const u64 w2p = pack2(wgt, wgt);
                    fa[0] = ffma2(w2p, h2f2p(q0.x), fa[0]);
                    fa[1] = ffma2(w2p, h2f2p(q0.y), fa[1]);
                    fa[2] = ffma2(w2p, h2f2p(q0.z), fa[2]);
                    fa[3] = ffma2(w2p, h2f2p(q0.w), fa[3]);
                    fa[4] = ffma2(w2p, h2f2p(q1.x), fa[4]);
                    fa[5] = ffma2(w2p, h2f2p(q1.y), fa[5]);
                    fa[6] = ffma2(w2p, h2f2p(q1.z), fa[6]);
                    fa[7] = ffma2(w2p, h2f2p(q1.w), fa[7]);
                }
            }
        }
    }

    const u64 third2 = pack2(1.0f / 3.0f, 1.0f / 3.0f);
    u64 feats2[8];
#pragma unroll
    for (int i = 0; i < 8; i++) feats2[i] = fmul2(fa[i], third2);

    // --- MLP 16 -> 64 -> 64 -> 17, packed f32x2, hidden stays in regs ---
    u64 a2[32];
#pragma unroll
    for (int k = 0; k < 32; k++) a2[k] = pack2(sB2[2 * k], sB2[2 * k + 1]);

#pragma unroll 2
    for (int j = 0; j < 64; j++) {
        u64 acc = 0ull;
        const u64* w1r = sW1p + j * 8;
#pragma unroll
        for (int c = 0; c < 8; c++) acc = ffma2(feats2[c], w1r[c], acc);
        float2 ac = unpack2(acc);
        float a = fmaxf(sB1[j] + ac.x + ac.y, 0.0f);
        const u64 aa = pack2(a, a);
        const u64* w2r = sW2p + j * 32;
#pragma unroll
        for (int k = 0; k < 32; k++) a2[k] = ffma2(aa, w2r[k], a2[k]);
    }

    u64 o2[8];
#pragma unroll
    for (int m = 0; m < 8; m++) o2[m] = pack2(sB3[2 * m], sB3[2 * m + 1]);
    float o16 = sB3[16];

#pragma unroll 2
    for (int k = 0; k < 32; k++) {
        float2 hh = unpack2(a2[k]);
        float h0 = fmaxf(hh.x, 0.0f);
        float h1 = fmaxf(hh.y, 0.0f);
        const u64 hj0 = pack2(h0, h0);
        const u64 hj1 = pack2(h1, h1);
        const u64* w3a = sW3p + (2 * k) * 8;
        const u64* w3b = sW3p + (2 * k + 1) * 8;
#pragma unroll
        for (int m = 0; m < 8; m++) {
            o2[m] = ffma2(hj0, w3a[m], o2[m]);
            o2[m] = ffma2(hj1, w3b[m], o2[m]);
        }
        o16 += h0 * sW3l[2 * k] + h1 * sW3l[2 * k + 1];
    }

    float o[17];
#pragma unroll
    for (int m = 0; m < 8; m++) {
        float2 tt = unpack2(o2[m]);
        o[2 * m] = tt.x; o[2 * m + 1] = tt.y;
    }
    o[16] = o16;
    float feats[16];
#pragma unroll
    for (int i = 0; i < 8; i++) {
        float2 ff = unpack2(feats2[i]);
        feats[2 * i] = ff.x; feats[2 * i + 1] = ff.y;
    }

    const float density = fmaxf(o[0], 0.0f);
    const float delta = (rt == 63) ? 1e10f : (zf - zn) * (1.0f / 63.0f);
    const float sd = density * delta;

    // Inclusive scan of sd across the 64 threads of this ray
    float vscan = sd;
#pragma unroll
    for (int off = 1; off < 32; off <<= 1) {
        float n = __shfl_up_sync(0xffffffffu, vscan, off);
        if (lane >= off) vscan += n;
    }
    if (lane == 31) sWS[rb][wr] = vscan;
    __syncthreads();
    const float cum = vscan + ((wr == 1) ? sWS[rb][0] : 0.0f);
    const float T = expf(-cum);
    const float alpha = 1.0f - expf(-sd);
    const float wgt = alpha * T;

#pragma unroll
    for (int c = 0; c < 16; c++) {
        float val = wgt * (feats[c] + o[c + 1]);
#pragma unroll
        for (int off = 16; off > 0; off >>= 1)
            val += __shfl_down_sync(0xffffffffu, val, off);
        if (lane == 0) sRed[rb][wr][c] = val;
    }
    __syncthreads();
    if (rt < 16) {
        g_rlo[((sv * kC + rt) * kHlo + py) * kWlo + px] =
            sRed[rb][0][rt] + sRed[rb][1][rt];
    }
}

// ---------------------------------------------------------------------------
// Kernel 3: 2x bilinear upsample, align_corners=True (48 -> 96)
// ---------------------------------------------------------------------------
__global__ void upsample_kernel(float* __restrict__ out) {
    const int n = blockIdx.x * blockDim.x + threadIdx.x;
    constexpr int kTot = kS * kVt * kC * kH * kW;
    if (n >= kTot) return;
    const int x = n % kW;
    const int y = (n / kW) % kH;
    const int svc = n / (kH * kW);

    const float pxf = (float)x * (47.0f / 95.0f);
    const float pyf = (float)y * (47.0f / 95.0f);
    const int lx = (int)pxf; const int hx = min(lx + 1, 47);
    const int ly = (int)pyf; const int hy = min(ly + 1, 47);
    const float fx = pxf - (float)lx;
    const float fy = pyf - (float)ly;

    const float* r = g_rlo + svc * (kHlo * kWlo);
    const float v00 = r[ly * kWlo + lx];
    const float v01 = r[ly * kWlo + hx];
    const float v10 = r[hy * kWlo + lx];
    const float v11 = r[hy * kWlo + hx];
    out[n] = (v00 * (1.0f - fx) + v01 * fx) * (1.0f - fy)
           + (v10 * (1.0f - fx) + v11 * fx) * fy;
}

// ---------------------------------------------------------------------------
extern "C" void kernel_launch(void* const* d_in, const int* in_sizes, int n_in,
                              void* d_out, int out_size) {
    const float* enc = (const float*)d_in[0];
    const float* ipo = (const float*)d_in[1];
    const float* tpo = (const float*)d_in[2];
    const float* fp  = (const float*)d_in[3];
    const float* znp = (const float*)d_in[4];
    const float* zfp = (const float*)d_in[5];
    const float* W1 = (const float*)d_in[7];
    const float* b1 = (const float*)d_in[8];
    const float* W2 = (const float*)d_in[9];
    const float* b2 = (const float*)d_in[10];
    const float* W3 = (const float*)d_in[11];
    const float* b3 = (const float*)d_in[12];
    float* out = (float*)d_out;

    transpose_kernel<<<(kNVox + 255) / 256, 256>>>(enc);
    render_kernel<<<kRays / 4, 256>>>(tpo, ipo, fp, znp, zfp,
                                      W1, b1, W2, b2, W3, b3);
    constexpr int kTot = kS * kVt * kC * kH * kW;
    upsample_kernel<<<(kTot + 255) / 256, 256>>>(out);
}

// round 3
// speedup vs baseline: 1.4365x; 1.0543x over previous
#include <cuda_runtime.h>
#include <cuda_fp16.h>

// Static problem shapes (from setup_inputs)
constexpr int kS   = 2;
constexpr int kVin = 3;
constexpr int kVt  = 4;
constexpr int kC   = 16;
constexpr int kD   = 64;
constexpr int kH   = 96;
constexpr int kW   = 96;
constexpr int kHlo = 48;
constexpr int kWlo = 48;

constexpr int kDHW  = kD * kH * kW;           // 589824
constexpr int kNVox = kS * kVin * kDHW;       // 3,538,944
constexpr int kRays = kS * kVt * kHlo * kWlo; // 18432

// Scratch: channel-last fp16 volume (113 MB, fits L2) + low-res renders
__device__ __half g_encT[(size_t)kNVox * kC];
__device__ float  g_rlo[kS * kVt * kC * kHlo * kWlo];

// ---------------- packed f32x2 helpers (sm_103a) ----------------
using u64 = unsigned long long;
__device__ __forceinline__ u64 pack2(float lo, float hi) {
    u64 r; asm("mov.b64 %0,{%1,%2};" : "=l"(r) : "f"(lo), "f"(hi)); return r;
}
__device__ __forceinline__ float2 unpack2(u64 v) {
    float2 f; asm("mov.b64 {%0,%1},%2;" : "=f"(f.x), "=f"(f.y) : "l"(v)); return f;
}
__device__ __forceinline__ u64 ffma2(u64 a, u64 b, u64 c) {
    u64 d; asm("fma.rn.f32x2 %0,%1,%2,%3;" : "=l"(d) : "l"(a), "l"(b), "l"(c)); return d;
}
__device__ __forceinline__ u64 fmul2(u64 a, u64 b) {
    u64 d; asm("mul.rn.f32x2 %0,%1,%2;" : "=l"(d) : "l"(a), "l"(b)); return d;
}
__device__ __forceinline__ u64 h2f2p(unsigned u) {
    __half2 h = *reinterpret_cast<__half2*>(&u);
    float2 f = __half22float2(h);
    return pack2(f.x, f.y);
}

// ---------------------------------------------------------------------------
// Kernel 1: transpose encoded_imgs (S,Vin,C,D,H,W) fp32 -> (S*Vin,D,H,W,C) fp16
// ---------------------------------------------------------------------------
__global__ void transpose_kernel(const float* __restrict__ enc) {
    int vox = blockIdx.x * blockDim.x + threadIdx.x;
    if (vox >= kNVox) return;
    int sv = vox / kDHW;
    int p  = vox - sv * kDHW;
    const float* src = enc + sv * (kC * kDHW) + p;
    unsigned h[8];
#pragma unroll
    for (int i = 0; i < 8; i++) {
        float a = src[(2 * i) * kDHW];
        float b = src[(2 * i + 1) * kDHW];
        __half2 hh = __floats2half2_rn(a, b);
        h[i] = *reinterpret_cast<unsigned*>(&hh);
    }
    uint4* dst = reinterpret_cast<uint4*>(g_encT + (size_t)vox * kC);
    dst[0] = make_uint4(h[0], h[1], h[2], h[3]);
    dst[1] = make_uint4(h[4], h[5], h[6], h[7]);
}

// ---------------------------------------------------------------------------
// Kernel 2: fused ray kernel. Block = 256 threads = 4 rays x 64 samples.
// Gather is fully branch-free: OOB corners get weight 0 and clamped (valid)
// addresses, so all 16 loads per view are straight-line and front-batched.
// ---------------------------------------------------------------------------
__global__ __launch_bounds__(256, 2) void render_kernel(
    const float* __restrict__ tposes,
    const float* __restrict__ iposes,
    const float* __restrict__ fp,
    const float* __restrict__ znp,
    const float* __restrict__ zfp,
    const float* __restrict__ W1, const float* __restrict__ b1,
    const float* __restrict__ W2, const float* __restrict__ b2,
    const float* __restrict__ W3, const float* __restrict__ b3)
{
    __shared__ u64   sW1p[64 * 8];    // [j][cpair]
    __shared__ u64   sW2p[64 * 32];   // [j][kpair]
    __shared__ u64   sW3p[64 * 8];    // [j][mpair]  (m=0..15)
    __shared__ float sW3l[64];        // W3[j][16]
    __shared__ float sB1[64], sB2[64], sB3[17];
    __shared__ float sWS[4][2];
    __shared__ float sRed[4][2][16];

    const int tid = threadIdx.x;

    // Stage weights (packed) into shared
    for (int i = tid; i < 512; i += 256) {
        int j = i >> 3, cp = i & 7;
        sW1p[i] = pack2(W1[(2 * cp) * 64 + j], W1[(2 * cp + 1) * 64 + j]);
    }
    {
        const u64* W2u = reinterpret_cast<const u64*>(W2);
        for (int i = tid; i < 2048; i += 256) sW2p[i] = W2u[i];
    }
    for (int i = tid; i < 512; i += 256) {
        int j = i >> 3, mp = i & 7;
        sW3p[i] = pack2(W3[j * 17 + 2 * mp], W3[j * 17 + 2 * mp + 1]);
    }
    if (tid < 64) {
        sB1[tid] = b1[tid];
        sB2[tid] = b2[tid];
        sW3l[tid] = W3[tid * 17 + 16];
    }
    if (tid < 17) sB3[tid] = b3[tid];
    __syncthreads();

    const int rb = tid >> 6;          // ray within block (0..3)
    const int rt = tid & 63;          // sample index along ray
    const int lane = rt & 31;
    const int wr = rt >> 5;

    const int ray = blockIdx.x * 4 + rb;
    const int sv  = ray / (kHlo * kWlo);
    const int pix = ray - sv * (kHlo * kWlo);
    const int py  = pix / kWlo;
    const int px  = pix - py * kWlo;
    const int s   = sv / kVt;

    const float focal = *fp;
    const float zn = *znp, zf = *zfp;

    const float* P = tposes + sv * 16;
    const float dcx = ((((float)px + 0.5f) / kWlo) * 2.0f - 1.0f) / focal;
    const float dcy = -(((((float)py + 0.5f) / kHlo) * 2.0f - 1.0f) / focal);
    const float dcz = -1.0f;
    const float dirx = P[0] * dcx + P[1] * dcy + P[2]  * dcz;
    const float diry = P[4] * dcx + P[5] * dcy + P[6]  * dcz;
    const float dirz = P[8] * dcx + P[9] * dcy + P[10] * dcz;

    const float t = zn + (zf - zn) * ((float)rt / 63.0f);
    const float ptx = P[3] + t * dirx;
    const float pty = P[7] + t * diry;
    const float ptz = P[11] + t * dirz;

    const float minz = focal * zn;
    const float maxz = focal * zf;
    const float wdscale = 2.0f / (maxz - minz);

    // --- 3-view trilinear gather (channel-last fp16 volume), branch-free ---
    u64 fa[8];
#pragma unroll
    for (int i = 0; i < 8; i++) fa[i] = 0ull;

#pragma unroll
    for (int v = 0; v < kVin; v++) {
        const float* IP = iposes + (s * kVin + v) * 16;
        const float dx = ptx - IP[3];
        const float dy = pty - IP[7];
        const float dz = ptz - IP[11];
        const float lx = IP[0] * dx + IP[4] * dy + IP[8]  * dz;
        const float ly = IP[1] * dx + IP[5] * dy + IP[9]  * dz;
        const float lz = IP[2] * dx + IP[6] * dy + IP[10] * dz;
        const float z  = -lz;
        const float invz = focal / z;
        const float gx = lx * invz;
        const float gy = -(ly * invz);
        const float gz = -((z - minz) * wdscale - 1.0f);

        const float ixf = (gx + 1.0f) * (0.5f * kW) - 0.5f;
        const float iyf = (gy + 1.0f) * (0.5f * kH) - 0.5f;
        const float izf = (gz + 1.0f) * (0.5f * kD) - 0.5f;

        const float xf0 = floorf(ixf), yf0 = floorf(iyf), zf0 = floorf(izf);
        const int ix0 = (int)xf0, iy0 = (int)yf0, iz0 = (int)zf0;
        const int ix1 = ix0 + 1, iy1 = iy0 + 1, iz1 = iz0 + 1;
        const float fx = ixf - xf0, fy = iyf - yf0, fz = izf - zf0;

        // validity-zeroed weights + clamped indices (no branches)
        const float wx0 = (ix0 >= 0 && ix0 < kW) ? (1.0f - fx) : 0.0f;
        const float wx1 = (ix1 >= 0 && ix1 < kW) ? fx : 0.0f;
        const float wy0 = (iy0 >= 0 && iy0 < kH) ? (1.0f - fy) : 0.0f;
        const float wy1 = (iy1 >= 0 && iy1 < kH) ? fy : 0.0f;
        const float wz0 = (iz0 >= 0 && iz0 < kD) ? (1.0f - fz) : 0.0f;
        const float wz1 = (iz1 >= 0 && iz1 < kD) ? fz : 0.0f;
        const int xi0 = min(max(ix0, 0), kW - 1);
        const int xi1 = min(max(ix1, 0), kW - 1);
        const int yi0 = min(max(iy0, 0), kH - 1);
        const int yi1 = min(max(iy1, 0), kH - 1);
        const int zi0 = min(max(iz0, 0), kD - 1);
        const int zi1 = min(max(iz1, 0), kD - 1);

        const int svin = s * kVin + v;
        const int rb00 = ((svin * kD + zi0) * kH + yi0) * kW;
        const int rb01 = ((svin * kD + zi0) * kH + yi1) * kW;
        const int rb10 = ((svin * kD + zi1) * kH + yi0) * kW;
        const int rb11 = ((svin * kD + zi1) * kH + yi1) * kW;

        const int   rowb[4] = { rb00, rb01, rb10, rb11 };
        const float wzy[4]  = { wz0 * wy0, wz0 * wy1, wz1 * wy0, wz1 * wy1 };

#pragma unroll
        for (int e = 0; e < 4; e++) {
            const uint4* p0 = reinterpret_cast<const uint4*>(
                g_encT + (size_t)(rowb[e] + xi0) * kC);
            const uint4* p1 = reinterpret_cast<const uint4*>(
                g_encT + (size_t)(rowb[e] + xi1) * kC);
            uint4 a0 = p0[0], a1 = p0[1];
            uint4 b0 = p1[0], b1 = p1[1];
            const u64 w0 = pack2(wzy[e] * wx0, wzy[e] * wx0);
            const u64 w1 = pack2(wzy[e] * wx1, wzy[e] * wx1);
            fa[0] = ffma2(w0, h2f2p(a0.x), fa[0]);
            fa[1] = ffma2(w0, h2f2p(a0.y), fa[1]);
            fa[2] = ffma2(w0, h2f2p(a0.z), fa[2]);
            fa[3] = ffma2(w0, h2f2p(a0.w), fa[3]);
            fa[4] = ffma2(w0, h2f2p(a1.x), fa[4]);
            fa[5] = ffma2(w0, h2f2p(a1.y), fa[5]);
            fa[6] = ffma2(w0, h2f2p(a1.z), fa[6]);
            fa[7] = ffma2(w0, h2f2p(a1.w), fa[7]);
            fa[0] = ffma2(w1, h2f2p(b0.x), fa[0]);
            fa[1] = ffma2(w1, h2f2p(b0.y), fa[1]);
            fa[2] = ffma2(w1, h2f2p(b0.z), fa[2]);
            fa[3] = ffma2(w1, h2f2p(b0.w), fa[3]);
            fa[4] = ffma2(w1, h2f2p(b1.x), fa[4]);
            fa[5] = ffma2(w1, h2f2p(b1.y), fa[5]);
            fa[6] = ffma2(w1, h2f2p(b1.z), fa[6]);
            fa[7] = ffma2(w1, h2f2p(b1.w), fa[7]);
        }
    }

    const u64 third2 = pack2(1.0f / 3.0f, 1.0f / 3.0f);
    u64 feats2[8];
#pragma unroll
    for (int i = 0; i < 8; i++) feats2[i] = fmul2(fa[i], third2);

    // --- MLP 16 -> 64 -> 64 -> 17, packed f32x2, hidden stays in regs ---
    u64 a2[32];
#pragma unroll
    for (int k = 0; k < 32; k++) a2[k] = pack2(sB2[2 * k], sB2[2 * k + 1]);

#pragma unroll 2
    for (int j = 0; j < 64; j++) {
        u64 acc = 0ull;
        const u64* w1r = sW1p + j * 8;
#pragma unroll
        for (int c = 0; c < 8; c++) acc = ffma2(feats2[c], w1r[c], acc);
        float2 ac = unpack2(acc);
        float a = fmaxf(sB1[j] + ac.x + ac.y, 0.0f);
        const u64 aa = pack2(a, a);
        const u64* w2r = sW2p + j * 32;
#pragma unroll
        for (int k = 0; k < 32; k++) a2[k] = ffma2(aa, w2r[k], a2[k]);
    }

    u64 o2[8];
#pragma unroll
    for (int m = 0; m < 8; m++) o2[m] = pack2(sB3[2 * m], sB3[2 * m + 1]);
    float o16 = sB3[16];

#pragma unroll 2
    for (int k = 0; k < 32; k++) {
        float2 hh = unpack2(a2[k]);
        float h0 = fmaxf(hh.x, 0.0f);
        float h1 = fmaxf(hh.y, 0.0f);
        const u64 hj0 = pack2(h0, h0);
        const u64 hj1 = pack2(h1, h1);
        const u64* w3a = sW3p + (2 * k) * 8;
        const u64* w3b = sW3p + (2 * k + 1) * 8;
#pragma unroll
        for (int m = 0; m < 8; m++) {
            o2[m] = ffma2(hj0, w3a[m], o2[m]);
            o2[m] = ffma2(hj1, w3b[m], o2[m]);
        }
        o16 += h0 * sW3l[2 * k] + h1 * sW3l[2 * k + 1];
    }

    float o[17];
#pragma unroll
    for (int m = 0; m < 8; m++) {
        float2 tt = unpack2(o2[m]);
        o[2 * m] = tt.x; o[2 * m + 1] = tt.y;
    }
    o[16] = o16;
    float feats[16];
#pragma unroll
    for (int i = 0; i < 8; i++) {
        float2 ff = unpack2(feats2[i]);
        feats[2 * i] = ff.x; feats[2 * i + 1] = ff.y;
    }

    const float density = fmaxf(o[0], 0.0f);
    const float delta = (rt == 63) ? 1e10f : (zf - zn) * (1.0f / 63.0f);
    const float sd = density * delta;

    // Inclusive scan of sd across the 64 threads of this ray
    float vscan = sd;
#pragma unroll
    for (int off = 1; off < 32; off <<= 1) {
        float n = __shfl_up_sync(0xffffffffu, vscan, off);
        if (lane >= off) vscan += n;
    }
    if (lane == 31) sWS[rb][wr] = vscan;
    __syncthreads();
    const float cum = vscan + ((wr == 1) ? sWS[rb][0] : 0.0f);
    const float T = expf(-cum);
    const float alpha = 1.0f - expf(-sd);
    const float wgt = alpha * T;

#pragma unroll
    for (int c = 0; c < 16; c++) {
        float val = wgt * (feats[c] + o[c + 1]);
#pragma unroll
        for (int off = 16; off > 0; off >>= 1)
            val += __shfl_down_sync(0xffffffffu, val, off);
        if (lane == 0) sRed[rb][wr][c] = val;
    }
    __syncthreads();
    if (rt < 16) {
        g_rlo[((sv * kC + rt) * kHlo + py) * kWlo + px] =
            sRed[rb][0][rt] + sRed[rb][1][rt];
    }
}

// ---------------------------------------------------------------------------
// Kernel 3: 2x bilinear upsample, align_corners=True (48 -> 96)
// ---------------------------------------------------------------------------
__global__ void upsample_kernel(float* __restrict__ out) {
    const int n = blockIdx.x * blockDim.x + threadIdx.x;
    constexpr int kTot = kS * kVt * kC * kH * kW;
    if (n >= kTot) return;
    const int x = n % kW;
    const int y = (n / kW) % kH;
    const int svc = n / (kH * kW);

    const float pxf = (float)x * (47.0f / 95.0f);
    const float pyf = (float)y * (47.0f / 95.0f);
    const int lx = (int)pxf; const int hx = min(lx + 1, 47);
    const int ly = (int)pyf; const int hy = min(ly + 1, 47);
    const float fx = pxf - (float)lx;
    const float fy = pyf - (float)ly;

    const float* r = g_rlo + svc * (kHlo * kWlo);
    const float v00 = r[ly * kWlo + lx];
    const float v01 = r[ly * kWlo + hx];
    const float v10 = r[hy * kWlo + lx];
    const float v11 = r[hy * kWlo + hx];
    out[n] = (v00 * (1.0f - fx) + v01 * fx) * (1.0f - fy)
           + (v10 * (1.0f - fx) + v11 * fx) * fy;
}

// ---------------------------------------------------------------------------
extern "C" void kernel_launch(void* const* d_in, const int* in_sizes, int n_in,
                              void* d_out, int out_size) {
    const float* enc = (const float*)d_in[0];
    const float* ipo = (const float*)d_in[1];
    const float* tpo = (const float*)d_in[2];
    const float* fp  = (const float*)d_in[3];
    const float* znp = (const float*)d_in[4];
    const float* zfp = (const float*)d_in[5];
    const float* W1 = (const float*)d_in[7];
    const float* b1 = (const float*)d_in[8];
    const float* W2 = (const float*)d_in[9];
    const float* b2 = (const float*)d_in[10];
    const float* W3 = (const float*)d_in[11];
    const float* b3 = (const float*)d_in[12];
    float* out = (float*)d_out;

    transpose_kernel<<<(kNVox + 255) / 256, 256>>>(enc);
    render_kernel<<<kRays / 4, 256>>>(tpo, ipo, fp, znp, zfp,
                                      W1, b1, W2, b2, W3, b3);
    constexpr int kTot = kS * kVt * kC * kH * kW;
    upsample_kernel<<<(kTot + 255) / 256, 256>>>(out);
}